// round 3
// baseline (speedup 1.0000x reference)
#include <cuda_runtime.h>
#include <math.h>

#define B_TOTAL 262144
#define TPB 256
#define NBLK (B_TOTAL / TPB)

// Per-layer smem block (floats): bias[64] | c0[64] (t-column) | Wf[64][64] | Wb[64][64]
#define WL_FLOATS (64 + 64 + 4096 + 4096)          // 8320
#define W_TOTAL (3 * WL_FLOATS)                    // 24960
#define HB_STRIDE 68                               // padded per-thread staging row
#define SMEM_FLOATS (W_TOTAL + TPB * HB_STRIDE)    // 24960 + 17408 = 42368
#define SMEM_BYTES (SMEM_FLOATS * 4)               // 169472 bytes

// Packed fp32x2 FMA: d(pair) += a(pair) * b(pair). Used only on continuous
// (non-mask-determining) paths.
__device__ __forceinline__ void ffma2(unsigned long long& d,
                                      unsigned long long a,
                                      unsigned long long b) {
    asm("fma.rn.f32x2 %0, %1, %2, %0;" : "+l"(d) : "l"(a), "l"(b));
}

__device__ __forceinline__ float pairsum(unsigned long long v) {
    float lo, hi;
    asm("mov.b64 {%0, %1}, %2;" : "=f"(lo), "=f"(hi) : "l"(v));
    return lo + hi;
}

__device__ __forceinline__ float2 unpk(unsigned long long v) {
    float lo, hi;
    asm("mov.b64 {%0, %1}, %2;" : "=f"(lo), "=f"(hi) : "l"(v));
    return make_float2(lo, hi);
}

// ---------------------------------------------------------------------------
// Sequential matvec replicating cuBLAS SGEMM rounding exactly:
//   acc = t*W[j][0]; for k ascending: acc = fmaf(x[k], W[j][k+1], acc);
//   s = acc + bias[j]  (single FADD, as in the XLA bias+relu fusion)
// Mask bit = (s > 0). This bitwise-matches the reference's pre-activation,
// eliminating ReLU mask flips (the source of the div-only 1.5e-3 error).
// ---------------------------------------------------------------------------
__device__ __forceinline__ void matvec64_seq(const float* __restrict__ W,     // [64][64] row-major smem
                                             const float* __restrict__ bias,  // [64]
                                             const float* __restrict__ c0,    // [64] t-column
                                             float t,
                                             const unsigned long long* __restrict__ xp,  // 32 pairs
                                             float* __restrict__ out,
                                             unsigned long long& mset) {
#pragma unroll 2
    for (int j = 0; j < 64; j += 2) {
        float a0 = t * c0[j];        // == fma(t, W[j][0], 0) rounding
        float a1 = t * c0[j + 1];
        const float4* w0 = (const float4*)(W + j * 64);
        const float4* w1 = (const float4*)(W + (j + 1) * 64);
#pragma unroll
        for (int q = 0; q < 16; q++) {
            float2 x0 = unpk(xp[2 * q]);
            float2 x1 = unpk(xp[2 * q + 1]);
            float4 v0 = w0[q];
            float4 v1 = w1[q];
            a0 = fmaf(x0.x, v0.x, a0);
            a0 = fmaf(x0.y, v0.y, a0);
            a0 = fmaf(x1.x, v0.z, a0);
            a0 = fmaf(x1.y, v0.w, a0);
            a1 = fmaf(x0.x, v1.x, a1);
            a1 = fmaf(x0.y, v1.y, a1);
            a1 = fmaf(x1.x, v1.z, a1);
            a1 = fmaf(x1.y, v1.w, a1);
        }
        float s0 = a0 + bias[j];
        float s1 = a1 + bias[j + 1];
        if (s0 > 0.0f) mset |= (1ull << j); else s0 = 0.0f;
        if (s1 > 0.0f) mset |= (1ull << (j + 1)); else s1 = 0.0f;
        out[j] = s0;
        out[j + 1] = s1;
    }
}

// ---------------------------------------------------------------------------
// Fast FFMA2 matvec for continuous paths.
// MODE 0: plain                 (u = W0c @ e)
// MODE 2: +bias +t*c0           (fwd layer 2 -> z_dot)
// MODE 3: apply existing relu mask (bwd g1, g0)
// ---------------------------------------------------------------------------
template <int MODE>
__device__ __forceinline__ void matvec64(const float* __restrict__ W,
                                         const float* __restrict__ bias,
                                         const float* __restrict__ c0,
                                         float t,
                                         const unsigned long long* __restrict__ xp,
                                         float* __restrict__ out,
                                         unsigned long long mapply) {
#pragma unroll 2
    for (int j = 0; j < 64; j += 2) {
        unsigned long long a0 = 0ull, a1 = 0ull;
        const ulonglong2* w0 = (const ulonglong2*)(W + j * 64);
        const ulonglong2* w1 = (const ulonglong2*)(W + (j + 1) * 64);
#pragma unroll
        for (int q = 0; q < 16; q++) {
            ulonglong2 v0 = w0[q];
            ulonglong2 v1 = w1[q];
            ffma2(a0, v0.x, xp[2 * q]);
            ffma2(a0, v0.y, xp[2 * q + 1]);
            ffma2(a1, v1.x, xp[2 * q]);
            ffma2(a1, v1.y, xp[2 * q + 1]);
        }
        float s0 = pairsum(a0);
        float s1 = pairsum(a1);
        if (MODE == 2) {
            s0 += bias[j] + t * c0[j];
            s1 += bias[j + 1] + t * c0[j + 1];
        }
        if (MODE == 3) {
            s0 = ((mapply >> j) & 1ull) ? s0 : 0.0f;
            s1 = ((mapply >> (j + 1)) & 1ull) ? s1 : 0.0f;
        }
        out[j] = s0;
        out[j + 1] = s1;
    }
}

__global__ void __launch_bounds__(TPB, 1)
ode_kernel(const float* __restrict__ tptr, const float* __restrict__ z,
           const float* __restrict__ e,
           const float* __restrict__ W0, const float* __restrict__ b0,
           const float* __restrict__ W1, const float* __restrict__ b1,
           const float* __restrict__ W2, const float* __restrict__ b2,
           float* __restrict__ zdot, float* __restrict__ negdiv) {
    extern __shared__ float sm[];
    const int tid = threadIdx.x;

    // ---- Stage weights: Wf[j][k] = W[j][k+1] (row-major), Wb[k][j] = W[j][k+1] (transpose) ----
    {
        const float* Wg[3] = {W0, W1, W2};
        const float* bgv[3] = {b0, b1, b2};
#pragma unroll
        for (int l = 0; l < 3; l++) {
            float* base = sm + l * WL_FLOATS;
            if (tid < 64) {
                base[tid] = bgv[l][tid];
                base[64 + tid] = Wg[l][tid * 65];  // t-column
            }
            for (int idx = tid; idx < 4096; idx += TPB) {
                int j = idx >> 6, k = idx & 63;
                float w = Wg[l][j * 65 + 1 + k];
                base[128 + j * 64 + k] = w;           // Wf
                base[128 + 4096 + k * 64 + j] = w;    // Wb
            }
        }
    }
    __syncthreads();

    const float t = tptr[0];
    const int row = blockIdx.x * TPB + tid;
    float* hb = sm + W_TOTAL + tid * HB_STRIDE;  // per-thread staging row (64 used, 68 stride)

    const float* L0 = sm;
    const float* L1 = sm + WL_FLOATS;
    const float* L2 = sm + 2 * WL_FLOATS;

    // ---- Load z as packed pairs ----
    unsigned long long hp[32];
    {
        const ulonglong2* zp = (const ulonglong2*)(z + (size_t)row * 64);
#pragma unroll
        for (int i = 0; i < 16; i++) {
            ulonglong2 v = zp[i];
            hp[2 * i] = v.x;
            hp[2 * i + 1] = v.y;
        }
    }

    unsigned long long m0 = 0ull, m1 = 0ull;

    // ---- Forward (layers 0,1 in reference-exact sequential order) ----
    matvec64_seq(L0 + 128, L0, L0 + 64, t, hp, hb, m0);
#pragma unroll
    for (int q = 0; q < 32; q++) hp[q] = *(const unsigned long long*)(hb + 2 * q);

    matvec64_seq(L1 + 128, L1, L1 + 64, t, hp, hb, m1);
#pragma unroll
    for (int q = 0; q < 32; q++) hp[q] = *(const unsigned long long*)(hb + 2 * q);

    matvec64<2>(L2 + 128, L2, L2 + 64, t, hp, hb, 0ull);  // z_dot staged in hb

    // ---- Coalesced z_dot flush (reads other threads' staging rows) ----
    __syncthreads();
    {
        float4* dst = (float4*)(zdot + (size_t)blockIdx.x * TPB * 64);
        for (int i4 = tid; i4 < TPB * 16; i4 += TPB) {
            int r = i4 >> 4, k4 = i4 & 15;
            dst[i4] = *(const float4*)(sm + W_TOTAL + r * HB_STRIDE + 4 * k4);
        }
    }
    __syncthreads();

    // ---- Backward ----
    unsigned long long ep[32];
    {
        const ulonglong2* eptr = (const ulonglong2*)(e + (size_t)row * 64);
#pragma unroll
        for (int i = 0; i < 16; i++) {
            ulonglong2 v = eptr[i];
            ep[2 * i] = v.x;
            ep[2 * i + 1] = v.y;
        }
    }

    // g1 = mask1 ⊙ (W2[:,1:]^T e)   — rows of Wb2
    matvec64<3>(L2 + 128 + 4096, L2, L2, 0.0f, ep, hb, m1);
    unsigned long long gp[32];
#pragma unroll
    for (int q = 0; q < 32; q++) gp[q] = *(const unsigned long long*)(hb + 2 * q);

    // u = W0[:,1:] @ e  (so div = g0·u, avoiding runtime-indexed e at the end)
    matvec64<0>(L0 + 128, L0, L0, 0.0f, ep, hb, 0ull);
    unsigned long long up[32];
#pragma unroll
    for (int q = 0; q < 32; q++) up[q] = *(const unsigned long long*)(hb + 2 * q);

    // g0 = mask0 ⊙ (W1[:,1:]^T g1) — rows of Wb1
    matvec64<3>(L1 + 128 + 4096, L1, L1, 0.0f, gp, hb, m0);
#pragma unroll
    for (int q = 0; q < 32; q++) gp[q] = *(const unsigned long long*)(hb + 2 * q);

    // div = g0 · u ; output is -div
    unsigned long long dp = 0ull;
#pragma unroll
    for (int q = 0; q < 32; q++) ffma2(dp, gp[q], up[q]);
    negdiv[row] = -pairsum(dp);
}

extern "C" void kernel_launch(void* const* d_in, const int* in_sizes, int n_in,
                              void* d_out, int out_size) {
    const float* t  = (const float*)d_in[0];
    const float* z  = (const float*)d_in[1];
    const float* e  = (const float*)d_in[2];
    const float* W0 = (const float*)d_in[3];
    const float* b0 = (const float*)d_in[4];
    const float* W1 = (const float*)d_in[5];
    const float* b1 = (const float*)d_in[6];
    const float* W2 = (const float*)d_in[7];
    const float* b2 = (const float*)d_in[8];

    float* zdot = (float*)d_out;                       // [B, 64]
    float* negdiv = zdot + (size_t)B_TOTAL * 64;       // [B, 1]

    cudaFuncSetAttribute(ode_kernel, cudaFuncAttributeMaxDynamicSharedMemorySize, SMEM_BYTES);
    ode_kernel<<<NBLK, TPB, SMEM_BYTES>>>(t, z, e, W0, b0, W1, b1, W2, b2, zdot, negdiv);
}

// round 4
// speedup vs baseline: 1.2355x; 1.2355x over previous
#include <cuda_runtime.h>

#define B_TOTAL 262144
#define TPB 128
#define ROWS_CTA 256
#define NBLK (B_TOTAL / ROWS_CTA)          // 1024

// Weights per layer: bias[64] | c0[64] (t-column) | Wf[64][64] row-major
#define WL_FLOATS (64 + 64 + 4096)         // 4224
#define W_TOTAL (3 * WL_FLOATS)            // 12672
#define HB_STRIDE 66                        // 64 used; 66 => conflict-free 64-bit staging ops
#define SLOT_FLOATS (ROWS_CTA * HB_STRIDE) // 16896
#define SMEM_FLOATS (W_TOTAL + 2 * SLOT_FLOATS)  // 46464
#define SMEM_BYTES (SMEM_FLOATS * 4)       // 185856 B -> 1 CTA/SM

typedef unsigned long long ull;

__device__ __forceinline__ void ffma2(ull& d, ull a, ull b) {
    asm("fma.rn.f32x2 %0, %1, %2, %0;" : "+l"(d) : "l"(a), "l"(b));
}
__device__ __forceinline__ float pairsum(ull v) {
    float lo, hi;
    asm("mov.b64 {%0, %1}, %2;" : "=f"(lo), "=f"(hi) : "l"(v));
    return lo + hi;
}
__device__ __forceinline__ ull pack2(float lo, float hi) {
    ull r;
    asm("mov.b64 %0, {%1, %2};" : "=l"(r) : "f"(lo), "f"(hi));
    return r;
}
// Zero pair lanes per relu-mask bits (2q, 2q+1). q is compile-time.
__device__ __forceinline__ ull maskpair(ull v, ull m, int q) {
    ull mm = (((m >> (2 * q)) & 1ull) * 0x00000000FFFFFFFFull)
           | (((m >> (2 * q + 1)) & 1ull) * 0xFFFFFFFF00000000ull);
    return v & mm;
}

// ---------------------------------------------------------------------------
// Dual-row sequential matvec (cuBLAS-exact rounding, mask-determining).
// Per-row chain is bit-identical to the R3 passing kernel; the two rows only
// share the broadcast weight loads.
// ---------------------------------------------------------------------------
__device__ __forceinline__ void matvec_seq_dual(
    const float* __restrict__ Wf, const float* __restrict__ bias,
    const float* __restrict__ c0, float t,
    const float2* __restrict__ x0, const float2* __restrict__ x1,  // 32 float2 each (regs)
    float* __restrict__ st0, float* __restrict__ st1,              // staging rows
    ull& m0, ull& m1) {
#pragma unroll 2
    for (int j = 0; j < 64; j += 2) {
        float c0j = t * c0[j], c1j = t * c0[j + 1];
        float a00 = c0j, a01 = c1j;   // row0: outputs j, j+1
        float a10 = c0j, a11 = c1j;   // row1
        const float4* w0 = (const float4*)(Wf + j * 64);
        const float4* w1 = (const float4*)(Wf + (j + 1) * 64);
#pragma unroll
        for (int q = 0; q < 16; q++) {
            float4 v0 = w0[q];
            float4 v1 = w1[q];
            float2 xa0 = x0[2 * q], xb0 = x0[2 * q + 1];
            float2 xa1 = x1[2 * q], xb1 = x1[2 * q + 1];
            a00 = fmaf(xa0.x, v0.x, a00); a00 = fmaf(xa0.y, v0.y, a00);
            a00 = fmaf(xb0.x, v0.z, a00); a00 = fmaf(xb0.y, v0.w, a00);
            a01 = fmaf(xa0.x, v1.x, a01); a01 = fmaf(xa0.y, v1.y, a01);
            a01 = fmaf(xb0.x, v1.z, a01); a01 = fmaf(xb0.y, v1.w, a01);
            a10 = fmaf(xa1.x, v0.x, a10); a10 = fmaf(xa1.y, v0.y, a10);
            a10 = fmaf(xb1.x, v0.z, a10); a10 = fmaf(xb1.y, v0.w, a10);
            a11 = fmaf(xa1.x, v1.x, a11); a11 = fmaf(xa1.y, v1.y, a11);
            a11 = fmaf(xb1.x, v1.z, a11); a11 = fmaf(xb1.y, v1.w, a11);
        }
        float s00 = a00 + bias[j], s01 = a01 + bias[j + 1];
        float s10 = a10 + bias[j], s11 = a11 + bias[j + 1];
        if (s00 > 0.0f) m0 |= (1ull << j); else s00 = 0.0f;
        if (s01 > 0.0f) m0 |= (1ull << (j + 1)); else s01 = 0.0f;
        if (s10 > 0.0f) m1 |= (1ull << j); else s10 = 0.0f;
        if (s11 > 0.0f) m1 |= (1ull << (j + 1)); else s11 = 0.0f;
        *(ull*)(st0 + j) = pack2(s00, s01);
        *(ull*)(st1 + j) = pack2(s10, s11);
    }
}

// ---------------------------------------------------------------------------
// Dual-row FFMA2 dot-form matvec (continuous path): out = W x (+ bias + t*c0).
// WITH_AFFINE=1 for forward layer 2 (z_dot); 0 for u = W0c @ e.
// ---------------------------------------------------------------------------
template <int WITH_AFFINE>
__device__ __forceinline__ void matvec_dot_dual(
    const float* __restrict__ Wf, const float* __restrict__ bias,
    const float* __restrict__ c0, float t,
    const ull* __restrict__ x0, const ull* __restrict__ x1,  // 32 pairs each (regs)
    float* __restrict__ st0, float* __restrict__ st1) {
#pragma unroll 1
    for (int j = 0; j < 64; j += 2) {
        ull a00 = 0ull, a01 = 0ull, a10 = 0ull, a11 = 0ull;
        const ulonglong2* w0 = (const ulonglong2*)(Wf + j * 64);
        const ulonglong2* w1 = (const ulonglong2*)(Wf + (j + 1) * 64);
#pragma unroll
        for (int q = 0; q < 16; q++) {
            ulonglong2 v0 = w0[q];
            ulonglong2 v1 = w1[q];
            ffma2(a00, v0.x, x0[2 * q]); ffma2(a00, v0.y, x0[2 * q + 1]);
            ffma2(a01, v1.x, x0[2 * q]); ffma2(a01, v1.y, x0[2 * q + 1]);
            ffma2(a10, v0.x, x1[2 * q]); ffma2(a10, v0.y, x1[2 * q + 1]);
            ffma2(a11, v1.x, x1[2 * q]); ffma2(a11, v1.y, x1[2 * q + 1]);
        }
        float s00 = pairsum(a00), s01 = pairsum(a01);
        float s10 = pairsum(a10), s11 = pairsum(a11);
        if (WITH_AFFINE) {
            float b0j = bias[j] + t * c0[j];
            float b1j = bias[j + 1] + t * c0[j + 1];
            s00 += b0j; s01 += b1j; s10 += b0j; s11 += b1j;
        }
        *(ull*)(st0 + j) = pack2(s00, s01);
        *(ull*)(st1 + j) = pack2(s10, s11);
    }
}

// ---------------------------------------------------------------------------
// Dual-row outer-product transpose-apply: acc[k] += sum_j in[j] * Wf[j][k].
// Inputs read scalar-wise from per-thread staging (no Wb copy needed).
// acc: 32 packed pairs per row, caller-owned registers.
// ---------------------------------------------------------------------------
__device__ __forceinline__ void bw_outer_dual(
    const float* __restrict__ Wf,
    const float* __restrict__ in0, const float* __restrict__ in1,  // staging rows
    ull* __restrict__ acc0, ull* __restrict__ acc1) {
#pragma unroll 1
    for (int j = 0; j < 64; j += 2) {
        float2 e0 = *(const float2*)(in0 + j);
        float2 e1 = *(const float2*)(in1 + j);
        ull e00 = pack2(e0.x, e0.x), e01 = pack2(e0.y, e0.y);
        ull e10 = pack2(e1.x, e1.x), e11 = pack2(e1.y, e1.y);
        const ulonglong2* w0 = (const ulonglong2*)(Wf + j * 64);
        const ulonglong2* w1 = (const ulonglong2*)(Wf + (j + 1) * 64);
#pragma unroll
        for (int q = 0; q < 16; q++) {
            ulonglong2 v0 = w0[q];
            ulonglong2 v1 = w1[q];
            ffma2(acc0[2 * q], e00, v0.x); ffma2(acc0[2 * q + 1], e00, v0.y);
            ffma2(acc1[2 * q], e10, v0.x); ffma2(acc1[2 * q + 1], e10, v0.y);
            ffma2(acc0[2 * q], e01, v1.x); ffma2(acc0[2 * q + 1], e01, v1.y);
            ffma2(acc1[2 * q], e11, v1.x); ffma2(acc1[2 * q + 1], e11, v1.y);
        }
    }
}

__global__ void __launch_bounds__(TPB, 1)
ode_kernel(const float* __restrict__ tptr, const float* __restrict__ z,
           const float* __restrict__ e,
           const float* __restrict__ W0, const float* __restrict__ b0,
           const float* __restrict__ W1, const float* __restrict__ b1,
           const float* __restrict__ W2, const float* __restrict__ b2,
           float* __restrict__ zdot, float* __restrict__ negdiv) {
    extern __shared__ float sm[];
    const int tid = threadIdx.x;

    // ---- Stage weights (row-major Wf only; backward uses outer products) ----
    {
        const float* Wg[3] = {W0, W1, W2};
        const float* bgv[3] = {b0, b1, b2};
#pragma unroll
        for (int l = 0; l < 3; l++) {
            float* base = sm + l * WL_FLOATS;
            if (tid < 64) {
                base[tid] = bgv[l][tid];
                base[64 + tid] = Wg[l][tid * 65];  // t-column
            }
            for (int idx = tid; idx < 4096; idx += TPB) {
                int j = idx >> 6, k = idx & 63;
                base[128 + j * 64 + k] = Wg[l][j * 65 + 1 + k];
            }
        }
    }
    __syncthreads();

    const float t = tptr[0];
    const int r0 = blockIdx.x * ROWS_CTA + tid;
    const int r1 = r0 + TPB;

    const float* L0 = sm;
    const float* L1 = sm + WL_FLOATS;
    const float* L2 = sm + 2 * WL_FLOATS;

    float* slotA = sm + W_TOTAL;                  // staging slot A (256 rows)
    float* slotB = slotA + SLOT_FLOATS;           // staging slot B
    float* stA0 = slotA + tid * HB_STRIDE;
    float* stA1 = slotA + (tid + TPB) * HB_STRIDE;
    float* stB0 = slotB + tid * HB_STRIDE;
    float* stB1 = slotB + (tid + TPB) * HB_STRIDE;

    ull mA0 = 0ull, mB0 = 0ull;   // relu masks layer0 (row0,row1)
    ull mA1 = 0ull, mB1 = 0ull;   // relu masks layer1

    // ---- Forward ----
    {
        float2 x0[32], x1[32];
        {
            const float4* zp0 = (const float4*)(z + (size_t)r0 * 64);
            const float4* zp1 = (const float4*)(z + (size_t)r1 * 64);
#pragma unroll
            for (int i = 0; i < 16; i++) {
                float4 v0 = zp0[i], v1 = zp1[i];
                x0[2 * i] = make_float2(v0.x, v0.y); x0[2 * i + 1] = make_float2(v0.z, v0.w);
                x1[2 * i] = make_float2(v1.x, v1.y); x1[2 * i + 1] = make_float2(v1.z, v1.w);
            }
        }
        matvec_seq_dual(L0 + 128, L0, L0 + 64, t, x0, x1, stA0, stA1, mA0, mB0);
#pragma unroll
        for (int q = 0; q < 32; q++) {
            x0[q] = *(const float2*)(stA0 + 2 * q);
            x1[q] = *(const float2*)(stA1 + 2 * q);
        }
        matvec_seq_dual(L1 + 128, L1, L1 + 64, t, x0, x1, stA0, stA1, mA1, mB1);

        ull h0[32], h1[32];
#pragma unroll
        for (int q = 0; q < 32; q++) {
            h0[q] = *(const ull*)(stA0 + 2 * q);
            h1[q] = *(const ull*)(stA1 + 2 * q);
        }
        matvec_dot_dual<1>(L2 + 128, L2, L2 + 64, t, h0, h1, stA0, stA1);  // z_dot -> slot A
    }

    // ---- Coalesced z_dot flush (reads other threads' staging rows) ----
    __syncthreads();
    {
        float4* dst = (float4*)(zdot + (size_t)blockIdx.x * ROWS_CTA * 64);
        for (int i4 = tid; i4 < ROWS_CTA * 16; i4 += TPB) {
            int r = i4 >> 4, c4 = i4 & 15;
            const float2* p = (const float2*)(slotA + r * HB_STRIDE + 4 * c4);
            float2 a = p[0], b = p[1];
            dst[i4] = make_float4(a.x, a.y, b.x, b.y);
        }
    }
    __syncthreads();

    // ---- Backward (staging rows below are per-thread private: no syncs) ----
    {
        // Load e: keep packed in regs for the u dot-matvec AND stage for outer use.
        ull ep0[32], ep1[32];
        {
            const float4* e0 = (const float4*)(e + (size_t)r0 * 64);
            const float4* e1 = (const float4*)(e + (size_t)r1 * 64);
#pragma unroll
            for (int i = 0; i < 16; i++) {
                float4 v0 = e0[i], v1 = e1[i];
                ep0[2 * i] = pack2(v0.x, v0.y); ep0[2 * i + 1] = pack2(v0.z, v0.w);
                ep1[2 * i] = pack2(v1.x, v1.y); ep1[2 * i + 1] = pack2(v1.z, v1.w);
                *(ull*)(stA0 + 4 * i) = ep0[2 * i]; *(ull*)(stA0 + 4 * i + 2) = ep0[2 * i + 1];
                *(ull*)(stA1 + 4 * i) = ep1[2 * i]; *(ull*)(stA1 + 4 * i + 2) = ep1[2 * i + 1];
            }
        }

        // u = W0[:,1:] @ e  (forward-apply, dot-form) -> slot B
        matvec_dot_dual<0>(L0 + 128, L0, L0 + 64, 0.0f, ep0, ep1, stB0, stB1);
    }
    {
        // g1 = mask1 .* (W2f^T e)  (outer form, e read from slot A) -> slot A
        ull acc0[32], acc1[32];
#pragma unroll
        for (int q = 0; q < 32; q++) { acc0[q] = 0ull; acc1[q] = 0ull; }
        bw_outer_dual(L2 + 128, stA0, stA1, acc0, acc1);
#pragma unroll
        for (int q = 0; q < 32; q++) {
            *(ull*)(stA0 + 2 * q) = maskpair(acc0[q], mA1, q);
            *(ull*)(stA1 + 2 * q) = maskpair(acc1[q], mB1, q);
        }
    }
    {
        // g0 = mask0 .* (W1f^T g1); div = g0 . u  (u from slot B)
        ull acc0[32], acc1[32];
#pragma unroll
        for (int q = 0; q < 32; q++) { acc0[q] = 0ull; acc1[q] = 0ull; }
        bw_outer_dual(L1 + 128, stA0, stA1, acc0, acc1);
        ull dp0 = 0ull, dp1 = 0ull;
#pragma unroll
        for (int q = 0; q < 32; q++) {
            ull g0 = maskpair(acc0[q], mA0, q);
            ull g1 = maskpair(acc1[q], mB0, q);
            ffma2(dp0, g0, *(const ull*)(stB0 + 2 * q));
            ffma2(dp1, g1, *(const ull*)(stB1 + 2 * q));
        }
        negdiv[r0] = -pairsum(dp0);
        negdiv[r1] = -pairsum(dp1);
    }
}

extern "C" void kernel_launch(void* const* d_in, const int* in_sizes, int n_in,
                              void* d_out, int out_size) {
    const float* t  = (const float*)d_in[0];
    const float* z  = (const float*)d_in[1];
    const float* e  = (const float*)d_in[2];
    const float* W0 = (const float*)d_in[3];
    const float* b0 = (const float*)d_in[4];
    const float* W1 = (const float*)d_in[5];
    const float* b1 = (const float*)d_in[6];
    const float* W2 = (const float*)d_in[7];
    const float* b2 = (const float*)d_in[8];

    float* zdot = (float*)d_out;                       // [B, 64]
    float* negdiv = zdot + (size_t)B_TOTAL * 64;       // [B, 1]

    cudaFuncSetAttribute(ode_kernel, cudaFuncAttributeMaxDynamicSharedMemorySize, SMEM_BYTES);
    ode_kernel<<<NBLK, TPB, SMEM_BYTES>>>(t, z, e, W0, b0, W1, b1, W2, b2, zdot, negdiv);
}